// round 1
// baseline (speedup 1.0000x reference)
#include <cuda_runtime.h>

// ---------------------------------------------------------------------------
// BinaryTreeRNN: out[i] = tree_combine( x[i,0:16] @ W_leaf^T + b_leaf )
// Precomputed params (setup kernel) + streaming main kernel (memory-bound).
// ---------------------------------------------------------------------------

struct Params {
    float2 Wp[4][16];   // [pair p][k] = (W_leaf[2p][k], W_leaf[2p+1][k])
    float2 bp[4];       // (b_leaf[2p], b_leaf[2p+1])
    // level 2 (8 -> 4): per node t: a*s + m*(l*r) + c*sin(s), then w*val + b
    float a2[4], m2[4], c2[4], w2v[4], b2v[4];
    // level 1 (4 -> 2)
    float a1[2], m1[2], c1[2], w1v[2], b1v[2];
    // level 0 (2 -> 1)
    float a0, m0, c0, w0v, b0v;
};

__device__ Params gP;

__device__ __forceinline__ void softmax_fold(const float* om, int row,
                                             float& a, float& m, float& c)
{
    float e0 = expf(om[row * 4 + 0]);
    float e1 = expf(om[row * 4 + 1]);
    float e2 = expf(om[row * 4 + 2]);
    float e3 = expf(om[row * 4 + 3]);
    float inv = 1.0f / (e0 + e1 + e2 + e3);
    a = (e0 + e3) * inv;   // sm0*s + sm3*s  ->  (sm0+sm3)*s
    m = e1 * inv;
    c = e2 * inv;
}

__global__ void setup_kernel(const float* __restrict__ W,
                             const float* __restrict__ bl,
                             const float* __restrict__ w0,
                             const float* __restrict__ w1,
                             const float* __restrict__ w2,
                             const float* __restrict__ b0,
                             const float* __restrict__ b1,
                             const float* __restrict__ b2,
                             const float* __restrict__ om0,
                             const float* __restrict__ om1,
                             const float* __restrict__ om2)
{
    if (threadIdx.x != 0 || blockIdx.x != 0) return;
    for (int p = 0; p < 4; p++) {
        for (int k = 0; k < 16; k++)
            gP.Wp[p][k] = make_float2(W[(2 * p) * 16 + k], W[(2 * p + 1) * 16 + k]);
        gP.bp[p] = make_float2(bl[2 * p], bl[2 * p + 1]);
    }
    for (int t = 0; t < 4; t++) {
        softmax_fold(om2, t, gP.a2[t], gP.m2[t], gP.c2[t]);
        gP.w2v[t] = w2[t];
        gP.b2v[t] = b2[t];
    }
    for (int t = 0; t < 2; t++) {
        softmax_fold(om1, t, gP.a1[t], gP.m1[t], gP.c1[t]);
        gP.w1v[t] = w1[t];
        gP.b1v[t] = b1[t];
    }
    softmax_fold(om0, 0, gP.a0, gP.m0, gP.c0);
    gP.w0v = w0[0];
    gP.b0v = b0[0];
}

// ---- packed fp32x2 helpers (sm_103a) --------------------------------------

__device__ __forceinline__ unsigned long long fma2(unsigned long long a,
                                                   unsigned long long b,
                                                   unsigned long long c)
{
    unsigned long long d;
    asm("fma.rn.f32x2 %0, %1, %2, %3;" : "=l"(d) : "l"(a), "l"(b), "l"(c));
    return d;
}

__device__ __forceinline__ unsigned long long dup2(float v)
{
    unsigned long long d;
    asm("mov.b64 %0, {%1, %1};" : "=l"(d) : "f"(v));
    return d;
}

__device__ __forceinline__ void unpack2(unsigned long long v, float& lo, float& hi)
{
    asm("mov.b64 {%0, %1}, %2;" : "=f"(lo), "=f"(hi) : "l"(v));
}

// ---- main kernel -----------------------------------------------------------

__global__ void __launch_bounds__(256, 8)
tree_rnn_kernel(const float4* __restrict__ x, float* __restrict__ out, int n)
{
    __shared__ Params sp;

    // cooperative param copy: sizeof(Params) = 684 B -> 171 words
    {
        const unsigned int* src = reinterpret_cast<const unsigned int*>(&gP);
        unsigned int* dst = reinterpret_cast<unsigned int*>(&sp);
        const int nwords = (int)(sizeof(Params) / 4);
        for (int i = threadIdx.x; i < nwords; i += blockDim.x) dst[i] = src[i];
    }
    __syncthreads();

    int i = blockIdx.x * blockDim.x + threadIdx.x;
    if (i >= n) return;

    // one row = 16 floats = 4 float4
    float4 v0 = x[(long long)i * 4 + 0];
    float4 v1 = x[(long long)i * 4 + 1];
    float4 v2 = x[(long long)i * 4 + 2];
    float4 v3 = x[(long long)i * 4 + 3];

    unsigned long long xb[16];
    xb[0]  = dup2(v0.x); xb[1]  = dup2(v0.y); xb[2]  = dup2(v0.z); xb[3]  = dup2(v0.w);
    xb[4]  = dup2(v1.x); xb[5]  = dup2(v1.y); xb[6]  = dup2(v1.z); xb[7]  = dup2(v1.w);
    xb[8]  = dup2(v2.x); xb[9]  = dup2(v2.y); xb[10] = dup2(v2.z); xb[11] = dup2(v2.w);
    xb[12] = dup2(v3.x); xb[13] = dup2(v3.y); xb[14] = dup2(v3.z); xb[15] = dup2(v3.w);

    // leaf matvec: h[2p], h[2p+1] accumulated in one packed register
    float h[8];
#pragma unroll
    for (int p = 0; p < 4; p++) {
        unsigned long long acc =
            *reinterpret_cast<const unsigned long long*>(&sp.bp[p]);
        const ulonglong2* wrow =
            reinterpret_cast<const ulonglong2*>(&sp.Wp[p][0]);
#pragma unroll
        for (int k2 = 0; k2 < 8; k2++) {
            ulonglong2 w = wrow[k2];           // LDS.128: two packed W pairs
            acc = fma2(w.x, xb[2 * k2 + 0], acc);
            acc = fma2(w.y, xb[2 * k2 + 1], acc);
        }
        unpack2(acc, h[2 * p + 0], h[2 * p + 1]);
    }

    // level 2: 8 -> 4
    float g[4];
#pragma unroll
    for (int t = 0; t < 4; t++) {
        float l = h[2 * t], r = h[2 * t + 1];
        float s = l + r;
        float val = sp.a2[t] * s + sp.m2[t] * (l * r) + sp.c2[t] * __sinf(s);
        g[t] = fmaf(sp.w2v[t], val, sp.b2v[t]);
    }

    // level 1: 4 -> 2
    float u[2];
#pragma unroll
    for (int t = 0; t < 2; t++) {
        float l = g[2 * t], r = g[2 * t + 1];
        float s = l + r;
        float val = sp.a1[t] * s + sp.m1[t] * (l * r) + sp.c1[t] * __sinf(s);
        u[t] = fmaf(sp.w1v[t], val, sp.b1v[t]);
    }

    // level 0: 2 -> 1
    {
        float l = u[0], r = u[1];
        float s = l + r;
        float val = sp.a0 * s + sp.m0 * (l * r) + sp.c0 * __sinf(s);
        out[i] = fmaf(sp.w0v, val, sp.b0v);
    }
}

extern "C" void kernel_launch(void* const* d_in, const int* in_sizes, int n_in,
                              void* d_out, int out_size)
{
    const float* x      = (const float*)d_in[0];
    const float* W_leaf = (const float*)d_in[1];
    const float* b_leaf = (const float*)d_in[2];
    const float* w0     = (const float*)d_in[3];
    const float* w1     = (const float*)d_in[4];
    const float* w2     = (const float*)d_in[5];
    const float* b0     = (const float*)d_in[6];
    const float* b1     = (const float*)d_in[7];
    const float* b2     = (const float*)d_in[8];
    const float* om0    = (const float*)d_in[9];
    const float* om1    = (const float*)d_in[10];
    const float* om2    = (const float*)d_in[11];

    int n = in_sizes[0] / 16;

    setup_kernel<<<1, 32>>>(W_leaf, b_leaf, w0, w1, w2, b0, b1, b2, om0, om1, om2);

    int threads = 256;
    int blocks = (n + threads - 1) / threads;
    tree_rnn_kernel<<<blocks, threads>>>(
        reinterpret_cast<const float4*>(x), (float*)d_out, n);
}

// round 2
// speedup vs baseline: 1.2516x; 1.2516x over previous
#include <cuda_runtime.h>

#define BLOCK 256

// ---------------------------------------------------------------------------
// BinaryTreeRNN: out[i] = tree_combine( x[i,0:16] @ W_leaf^T + b_leaf )
// Single kernel. Per-block param prep + coalesced swizzled x staging.
// ---------------------------------------------------------------------------

struct __align__(16) SmemLayout {
    float4 tile[BLOCK * 4];   // 256 rows x 16 floats, XOR-swizzled
    float2 Wp[4][16];         // [pair p][k] = (W[2p][k], W[2p+1][k])
    float2 bp[4];             // (b_leaf[2p], b_leaf[2p+1])
    float4 node[7];           // (A, M, C, b): val = A*s + M*l*r + C*sin(s) + b
};

// ---- packed fp32x2 helpers (sm_103a) --------------------------------------

__device__ __forceinline__ unsigned long long fma2(unsigned long long a,
                                                   unsigned long long b,
                                                   unsigned long long c)
{
    unsigned long long d;
    asm("fma.rn.f32x2 %0, %1, %2, %3;" : "=l"(d) : "l"(a), "l"(b), "l"(c));
    return d;
}

__device__ __forceinline__ unsigned long long dup2(float v)
{
    unsigned long long d;
    asm("mov.b64 %0, {%1, %1};" : "=l"(d) : "f"(v));
    return d;
}

__device__ __forceinline__ void unpack2(unsigned long long v, float& lo, float& hi)
{
    asm("mov.b64 {%0, %1}, %2;" : "=f"(lo), "=f"(hi) : "l"(v));
}

// ---- main kernel -----------------------------------------------------------

__global__ void __launch_bounds__(BLOCK)
tree_rnn_kernel(const float4* __restrict__ x4,
                float* __restrict__ out,
                int n,
                const float* __restrict__ W,
                const float* __restrict__ bl,
                const float* __restrict__ w0,
                const float* __restrict__ w1,
                const float* __restrict__ w2,
                const float* __restrict__ b0,
                const float* __restrict__ b1,
                const float* __restrict__ b2,
                const float* __restrict__ om0,
                const float* __restrict__ om1,
                const float* __restrict__ om2)
{
    __shared__ SmemLayout sm;
    const int t = threadIdx.x;

    // ---- Phase A: per-block param prep (reads tiny, L2-hot tensors) -------
    if (t < 64) {
        int p = t >> 4, k = t & 15;
        sm.Wp[p][k] = make_float2(W[(2 * p) * 16 + k], W[(2 * p + 1) * 16 + k]);
    } else if (t < 68) {
        int p = t - 64;
        sm.bp[p] = make_float2(bl[2 * p], bl[2 * p + 1]);
    } else if (t < 75) {
        int i = t - 68;   // node index: 0-3 level2, 4-5 level1, 6 level0
        const float* om;
        float w, b;
        if (i < 4)      { om = om2 + 4 * i;       w = w2[i];     b = b2[i]; }
        else if (i < 6) { om = om1 + 4 * (i - 4); w = w1[i - 4]; b = b1[i - 4]; }
        else            { om = om0;               w = w0[0];     b = b0[0]; }
        float e0 = expf(om[0]);
        float e1 = expf(om[1]);
        float e2 = expf(om[2]);
        float e3 = expf(om[3]);
        float inv = w / (e0 + e1 + e2 + e3);      // fold w into softmax coeffs
        sm.node[i] = make_float4((e0 + e3) * inv, e1 * inv, e2 * inv, b);
    }

    // ---- Phase B: coalesced tile load, XOR-swizzled store ------------------
    const int n4 = n * 4;
    const int base4 = blockIdx.x * (BLOCK * 4);
#pragma unroll
    for (int j = 0; j < 4; j++) {
        int li = j * BLOCK + t;                   // local float4 index
        int g4 = base4 + li;
        float4 v;
        if (g4 < n4) v = x4[g4];
        else         v = make_float4(0.f, 0.f, 0.f, 0.f);
        int r = li >> 2;                          // local row
        int q = li & 3;                           // quarter within row
        sm.tile[(r << 2) + (q ^ ((r >> 1) & 3))] = v;
    }
    __syncthreads();

    const int row = blockIdx.x * BLOCK + t;
    if (row >= n) return;

    // ---- gather own row (conflict-free via matching swizzle) --------------
    const int swz = (t >> 1) & 3;
    float4 v0 = sm.tile[(t << 2) + (0 ^ swz)];
    float4 v1 = sm.tile[(t << 2) + (1 ^ swz)];
    float4 v2 = sm.tile[(t << 2) + (2 ^ swz)];
    float4 v3 = sm.tile[(t << 2) + (3 ^ swz)];

    unsigned long long xb[16];
    xb[0]  = dup2(v0.x); xb[1]  = dup2(v0.y); xb[2]  = dup2(v0.z); xb[3]  = dup2(v0.w);
    xb[4]  = dup2(v1.x); xb[5]  = dup2(v1.y); xb[6]  = dup2(v1.z); xb[7]  = dup2(v1.w);
    xb[8]  = dup2(v2.x); xb[9]  = dup2(v2.y); xb[10] = dup2(v2.z); xb[11] = dup2(v2.w);
    xb[12] = dup2(v3.x); xb[13] = dup2(v3.y); xb[14] = dup2(v3.z); xb[15] = dup2(v3.w);

    // ---- leaf matvec: packed fp32x2, (h[2p], h[2p+1]) per register --------
    float h[8];
#pragma unroll
    for (int p = 0; p < 4; p++) {
        unsigned long long acc =
            *reinterpret_cast<const unsigned long long*>(&sm.bp[p]);
#pragma unroll
        for (int k2 = 0; k2 < 8; k2++) {
            ulonglong2 w = *reinterpret_cast<const ulonglong2*>(&sm.Wp[p][2 * k2]);
            acc = fma2(w.x, xb[2 * k2 + 0], acc);
            acc = fma2(w.y, xb[2 * k2 + 1], acc);
        }
        unpack2(acc, h[2 * p + 0], h[2 * p + 1]);
    }

    // ---- tree combine: val = A*s + M*(l*r) + C*sin(s) + b ------------------
    float g[4];
#pragma unroll
    for (int k = 0; k < 4; k++) {
        float4 np = sm.node[k];
        float l = h[2 * k], r = h[2 * k + 1];
        float s = l + r;
        g[k] = fmaf(np.x, s, fmaf(np.y, l * r, fmaf(np.z, __sinf(s), np.w)));
    }
    float u[2];
#pragma unroll
    for (int k = 0; k < 2; k++) {
        float4 np = sm.node[4 + k];
        float l = g[2 * k], r = g[2 * k + 1];
        float s = l + r;
        u[k] = fmaf(np.x, s, fmaf(np.y, l * r, fmaf(np.z, __sinf(s), np.w)));
    }
    {
        float4 np = sm.node[6];
        float l = u[0], r = u[1];
        float s = l + r;
        out[row] = fmaf(np.x, s, fmaf(np.y, l * r, fmaf(np.z, __sinf(s), np.w)));
    }
}

extern "C" void kernel_launch(void* const* d_in, const int* in_sizes, int n_in,
                              void* d_out, int out_size)
{
    const float* x      = (const float*)d_in[0];
    const float* W_leaf = (const float*)d_in[1];
    const float* b_leaf = (const float*)d_in[2];
    const float* w0     = (const float*)d_in[3];
    const float* w1     = (const float*)d_in[4];
    const float* w2     = (const float*)d_in[5];
    const float* b0     = (const float*)d_in[6];
    const float* b1     = (const float*)d_in[7];
    const float* b2     = (const float*)d_in[8];
    const float* om0    = (const float*)d_in[9];
    const float* om1    = (const float*)d_in[10];
    const float* om2    = (const float*)d_in[11];

    int n = in_sizes[0] / 16;
    int blocks = (n + BLOCK - 1) / BLOCK;

    tree_rnn_kernel<<<blocks, BLOCK>>>(
        reinterpret_cast<const float4*>(x), (float*)d_out, n,
        W_leaf, b_leaf, w0, w1, w2, b0, b1, b2, om0, om1, om2);
}

// round 3
// speedup vs baseline: 1.6458x; 1.3150x over previous
#include <cuda_runtime.h>

#define BLOCK 256

// ---------------------------------------------------------------------------
// BinaryTreeRNN: out[i] = tree_combine( x[i,0:16] @ W_leaf^T + b_leaf )
// Params folded into __constant__ (separate LDC/LDCU port, zero L1TEX phases).
// x staged through swizzled shared memory for coalesced LDG + conflict-free LDS.
// ---------------------------------------------------------------------------

struct __align__(16) CParams {
    float2 Wp[4][16];   // [pair p][k] = (W[2p][k], W[2p+1][k])
    float2 bp[4];       // (b_leaf[2p], b_leaf[2p+1])
    float4 node[7];     // (A, M, C, b): val = A*s + M*l*r + C*sin(s) + b
};

__constant__ CParams cP;
__device__ CParams gStage;

__global__ void setup_kernel(const float* __restrict__ W,
                             const float* __restrict__ bl,
                             const float* __restrict__ w0,
                             const float* __restrict__ w1,
                             const float* __restrict__ w2,
                             const float* __restrict__ b0,
                             const float* __restrict__ b1,
                             const float* __restrict__ b2,
                             const float* __restrict__ om0,
                             const float* __restrict__ om1,
                             const float* __restrict__ om2)
{
    int t = threadIdx.x;
    if (t < 64) {
        int p = t >> 4, k = t & 15;
        gStage.Wp[p][k] = make_float2(W[(2 * p) * 16 + k], W[(2 * p + 1) * 16 + k]);
    } else if (t < 68) {
        int p = t - 64;
        gStage.bp[p] = make_float2(bl[2 * p], bl[2 * p + 1]);
    } else if (t < 75) {
        int i = t - 68;   // 0-3: level2, 4-5: level1, 6: level0
        const float* om;
        float w, b;
        if (i < 4)      { om = om2 + 4 * i;       w = w2[i];     b = b2[i]; }
        else if (i < 6) { om = om1 + 4 * (i - 4); w = w1[i - 4]; b = b1[i - 4]; }
        else            { om = om0;               w = w0[0];     b = b0[0]; }
        float e0 = expf(om[0]);
        float e1 = expf(om[1]);
        float e2 = expf(om[2]);
        float e3 = expf(om[3]);
        float inv = w / (e0 + e1 + e2 + e3);   // fold w into softmax coeffs
        gStage.node[i] = make_float4((e0 + e3) * inv, e1 * inv, e2 * inv, b);
    }
}

// ---- packed fp32x2 helpers (sm_103a) --------------------------------------

__device__ __forceinline__ unsigned long long fma2(unsigned long long a,
                                                   unsigned long long b,
                                                   unsigned long long c)
{
    unsigned long long d;
    asm("fma.rn.f32x2 %0, %1, %2, %3;" : "=l"(d) : "l"(a), "l"(b), "l"(c));
    return d;
}

__device__ __forceinline__ unsigned long long dup2(float v)
{
    unsigned long long d;
    asm("mov.b64 %0, {%1, %1};" : "=l"(d) : "f"(v));
    return d;
}

__device__ __forceinline__ void unpack2(unsigned long long v, float& lo, float& hi)
{
    asm("mov.b64 {%0, %1}, %2;" : "=f"(lo), "=f"(hi) : "l"(v));
}

// ---- main kernel -----------------------------------------------------------

__global__ void __launch_bounds__(BLOCK)
tree_rnn_kernel(const float4* __restrict__ x4, float* __restrict__ out, int n)
{
    __shared__ float4 tile[BLOCK * 4];   // 256 rows x 16 floats, XOR-swizzled
    const int t = threadIdx.x;

    // coalesced tile load, XOR-swizzled store (conflict-free both phases)
    const int n4 = n * 4;
    const int base4 = blockIdx.x * (BLOCK * 4);
#pragma unroll
    for (int j = 0; j < 4; j++) {
        int li = j * BLOCK + t;
        int g4 = base4 + li;
        float4 v;
        if (g4 < n4) v = x4[g4];
        else         v = make_float4(0.f, 0.f, 0.f, 0.f);
        int r = li >> 2;
        int q = li & 3;
        tile[(r << 2) + (q ^ ((r >> 1) & 3))] = v;
    }
    __syncthreads();

    const int row = blockIdx.x * BLOCK + t;
    if (row >= n) return;

    // gather own row (conflict-free via matching swizzle)
    const int swz = (t >> 1) & 3;
    float4 v0 = tile[(t << 2) + (0 ^ swz)];
    float4 v1 = tile[(t << 2) + (1 ^ swz)];
    float4 v2 = tile[(t << 2) + (2 ^ swz)];
    float4 v3 = tile[(t << 2) + (3 ^ swz)];

    unsigned long long xb[16];
    xb[0]  = dup2(v0.x); xb[1]  = dup2(v0.y); xb[2]  = dup2(v0.z); xb[3]  = dup2(v0.w);
    xb[4]  = dup2(v1.x); xb[5]  = dup2(v1.y); xb[6]  = dup2(v1.z); xb[7]  = dup2(v1.w);
    xb[8]  = dup2(v2.x); xb[9]  = dup2(v2.y); xb[10] = dup2(v2.z); xb[11] = dup2(v2.w);
    xb[12] = dup2(v3.x); xb[13] = dup2(v3.y); xb[14] = dup2(v3.z); xb[15] = dup2(v3.w);

    // leaf matvec: weights from the constant port (no L1TEX traffic)
    float h[8];
#pragma unroll
    for (int p = 0; p < 4; p++) {
        unsigned long long acc =
            *reinterpret_cast<const unsigned long long*>(&cP.bp[p]);
#pragma unroll
        for (int k2 = 0; k2 < 8; k2++) {
            ulonglong2 w = *reinterpret_cast<const ulonglong2*>(&cP.Wp[p][2 * k2]);
            acc = fma2(w.x, xb[2 * k2 + 0], acc);
            acc = fma2(w.y, xb[2 * k2 + 1], acc);
        }
        unpack2(acc, h[2 * p + 0], h[2 * p + 1]);
    }

    // tree combine: val = A*s + M*(l*r) + C*sin(s) + b
    float g[4];
#pragma unroll
    for (int k = 0; k < 4; k++) {
        float4 np = cP.node[k];
        float l = h[2 * k], r = h[2 * k + 1];
        float s = l + r;
        g[k] = fmaf(np.x, s, fmaf(np.y, l * r, fmaf(np.z, __sinf(s), np.w)));
    }
    float u[2];
#pragma unroll
    for (int k = 0; k < 2; k++) {
        float4 np = cP.node[4 + k];
        float l = g[2 * k], r = g[2 * k + 1];
        float s = l + r;
        u[k] = fmaf(np.x, s, fmaf(np.y, l * r, fmaf(np.z, __sinf(s), np.w)));
    }
    {
        float4 np = cP.node[6];
        float l = u[0], r = u[1];
        float s = l + r;
        out[row] = fmaf(np.x, s, fmaf(np.y, l * r, fmaf(np.z, __sinf(s), np.w)));
    }
}

extern "C" void kernel_launch(void* const* d_in, const int* in_sizes, int n_in,
                              void* d_out, int out_size)
{
    const float* x      = (const float*)d_in[0];
    const float* W_leaf = (const float*)d_in[1];
    const float* b_leaf = (const float*)d_in[2];
    const float* w0     = (const float*)d_in[3];
    const float* w1     = (const float*)d_in[4];
    const float* w2     = (const float*)d_in[5];
    const float* b0     = (const float*)d_in[6];
    const float* b1     = (const float*)d_in[7];
    const float* b2     = (const float*)d_in[8];
    const float* om0    = (const float*)d_in[9];
    const float* om1    = (const float*)d_in[10];
    const float* om2    = (const float*)d_in[11];

    int n = in_sizes[0] / 16;

    // fold params on device, then copy into __constant__ (D2D, capture-legal)
    setup_kernel<<<1, 128>>>(W_leaf, b_leaf, w0, w1, w2, b0, b1, b2,
                             om0, om1, om2);
    void* stage_ptr = nullptr;
    cudaGetSymbolAddress(&stage_ptr, gStage);
    cudaMemcpyToSymbolAsync(cP, stage_ptr, sizeof(CParams), 0,
                            cudaMemcpyDeviceToDevice);

    int blocks = (n + BLOCK - 1) / BLOCK;
    tree_rnn_kernel<<<blocks, BLOCK>>>(
        reinterpret_cast<const float4*>(x), (float*)d_out, n);
}